// round 10
// baseline (speedup 1.0000x reference)
#include <cuda_runtime.h>
#include <cuda_bf16.h>
#include <math.h>

// Problem constants
#define B    512
#define T    365
#define INP  10
#define H    256
#define OUT  20

// 4 batch groups x 32 column groups = 128 persistent CTAs.
// 512 threads = 2 k-split teams x 8 warps; warp w2 = M-tile (16 rows).
#define GB        4
#define GC        32
#define NCTA      (GB * GC)
#define NTHREADS  512

// A-fragment arrays: [buf2][gb4][mtile8][kstep16][split2][lane32] x uint4
#define HA_ELEMS  (2 * 4 * 8 * 16 * 2 * 32)

__device__ uint4 g_hA0[HA_ELEMS];
__device__ uint4 g_hA1[HA_ELEMS];
__device__ float g_hfin[B * H];
__device__ unsigned g_cnt[GB];
__device__ unsigned g_gen[GB];
__device__ unsigned g_cnt_all;
__device__ unsigned g_gen_all;

__device__ __forceinline__ int ha_idx(int buf, int gb, int mt, int ks, int sp, int l) {
    return (((((buf * 4 + gb) * 8 + mt) * 16 + ks) * 2 + sp) * 32 + l);
}

__device__ __forceinline__ void barrier_sync(unsigned* cnt, unsigned* gen, unsigned target) {
    __threadfence();
    __syncthreads();
    if (threadIdx.x == 0) {
        unsigned g = *(volatile unsigned*)gen;
        if (atomicAdd(cnt, 1u) == target - 1u) {
            *cnt = 0u;
            __threadfence();
            atomicAdd(gen, 1u);
        } else {
            while (*(volatile unsigned*)gen == g) { }
        }
    }
    __syncthreads();
}

// mma.sync m16n8k16 row.col f32.bf16.bf16.f32, accumulate in place.
__device__ __forceinline__ void mma_bf16(float* d, unsigned a0, unsigned a1,
                                         unsigned a2, unsigned a3,
                                         unsigned b0, unsigned b1) {
    asm volatile(
        "mma.sync.aligned.m16n8k16.row.col.f32.bf16.bf16.f32 "
        "{%0,%1,%2,%3}, {%4,%5,%6,%7}, {%8,%9}, {%0,%1,%2,%3};"
        : "+f"(d[0]), "+f"(d[1]), "+f"(d[2]), "+f"(d[3])
        : "r"(a0), "r"(a1), "r"(a2), "r"(a3), "r"(b0), "r"(b1));
}

// Split two fp32 into packed bf16x2 (hi) + packed bf16x2 (lo residual).
__device__ __forceinline__ void split2(float a, float b, unsigned& hi, unsigned& lo) {
    __nv_bfloat16 ah = __float2bfloat16_rn(a), bh = __float2bfloat16_rn(b);
    __nv_bfloat16 al = __float2bfloat16_rn(a - __bfloat162float(ah));
    __nv_bfloat16 bl = __float2bfloat16_rn(b - __bfloat162float(bh));
    __nv_bfloat162 h2; h2.x = ah; h2.y = bh;
    __nv_bfloat162 l2; l2.x = al; l2.y = bl;
    hi = *reinterpret_cast<unsigned*>(&h2);
    lo = *reinterpret_cast<unsigned*>(&l2);
}

// Fast gate math (MUFU.EX2-based, ~1e-6 rel error; tolerance is 1e-3).
__device__ __forceinline__ float fsig(float v) {
    return 1.0f / (1.0f + __expf(-v));
}
__device__ __forceinline__ float ftanh_(float v) {
    return 2.0f / (1.0f + __expf(-2.0f * v)) - 1.0f;
}

// Weight frags: sets s (0=hh0, 1=hh1, 2=ih1) x 3 ntiles x 16 ksteps x 32 lanes,
// uint4 = {b0_hi, b1_hi, b0_lo, b1_lo}. 4608 x 16B = 72 KB.
#define NWB (3 * 3 * 16 * 32)
// Reduction buffer: 256 threads x 36 floats (9 float4), stride 36 -> conflict-free.
#define REDF (256 * 36)

__global__ void __launch_bounds__(NTHREADS, 1)
gru_tc_kernel(const float* __restrict__ x,
              const float* __restrict__ W_ih0, const float* __restrict__ W_hh0,
              const float* __restrict__ b_ih0, const float* __restrict__ b_hh0,
              const float* __restrict__ W_ih1, const float* __restrict__ W_hh1,
              const float* __restrict__ b_ih1, const float* __restrict__ b_hh1,
              const float* __restrict__ W_out, const float* __restrict__ b_out,
              float* __restrict__ out) {
    extern __shared__ char smraw[];
    uint4* sWB  = reinterpret_cast<uint4*>(smraw);         // NWB x 16B
    float* red  = reinterpret_cast<float*>(sWB + NWB);     // REDF
    float* sx   = red + REDF;                              // 128*12
    float* sWi0 = sx + 128 * 12;                           // 24*12
    float* sBi0 = sWi0 + 24 * 12;                          // 24 each
    float* sBh0 = sBi0 + 24;
    float* sBi1 = sBh0 + 24;
    float* sBh1 = sBi1 + 24;

    const int tid  = threadIdx.x;
    const int team = tid >> 8;             // k-split team 0/1
    const int t2   = tid & 255;
    const int w2   = t2 >> 5;              // M-tile 0..7
    const int l    = t2 & 31;              // lane
    const int g    = l >> 2;               // frag row group 0..7
    const int c    = l & 3;                // frag col pair 0..3
    const int gb   = blockIdx.x >> 5;      // batch group
    const int gc   = blockIdx.x & 31;      // column group
    const int c0   = gc * 8;
    const int gb0  = gb * 128;
    const int ksW  = gc >> 1;              // kstep our h-cols land in
    const int wboff = 8 * (gc & 1);        // byte offset within 16B frag slot
    const int ksB  = team * 8;             // this team's kstep base

    // ---- Prologue: pack weights into B-fragment layout (hi/lo split) ----
    {
        const float* Wsets[3] = { W_hh0, W_hh1, W_ih1 };
        for (int e = tid; e < NWB; e += NTHREADS) {
            int lane = e & 31;
            int ks   = (e >> 5) & 15;
            int rest = e >> 9;
            int n    = rest % 3;
            int s    = rest / 3;
            int t4 = lane & 3, nn = lane >> 2;
            const float* Wp = Wsets[s] + (size_t)(n * H + c0 + nn) * H + ks * 16;
            float w00 = Wp[2 * t4],     w01 = Wp[2 * t4 + 1];
            float w10 = Wp[8 + 2 * t4], w11 = Wp[9 + 2 * t4];
            uint4 v;
            split2(w00, w01, v.x, v.z);
            split2(w10, w11, v.y, v.w);
            sWB[e] = v;
        }
    }
    for (int idx = tid; idx < 24 * INP; idx += NTHREADS) {
        int row = idx / INP, i = idx - row * INP;
        int gg = row >> 3, j = row & 7;
        sWi0[row * 12 + i] = W_ih0[(gg * H + c0 + j) * INP + i];
    }
    if (tid < 24) {
        int gg = tid >> 3, j = tid & 7;
        int grow = gg * H + c0 + j;
        sBi0[tid] = b_ih0[grow];
        sBh0[tid] = b_hh0[grow];
        sBi1[tid] = b_ih1[grow];
        sBh1[tid] = b_hh1[grow];
    }

    // Zero A-frag buffers; every launch (determinism).
    {
        uint4 z4 = make_uint4(0u, 0u, 0u, 0u);
        for (int i = blockIdx.x * NTHREADS + tid; i < HA_ELEMS; i += NCTA * NTHREADS) {
            g_hA0[i] = z4;
            g_hA1[i] = z4;
        }
    }
    barrier_sync(&g_cnt_all, &g_gen_all, NCTA);

    // Team-0 threads own the hidden state (4 D-frag positions each).
    float h0reg[4] = {0.f, 0.f, 0.f, 0.f};
    float h1reg[4] = {0.f, 0.f, 0.f, 0.f};

    // ---- Pipelined loop: iter i computes h0[i] AND h1[i-1]; one barrier/iter.
    for (int i = 0; i <= T; ++i) {
        const int bufR = i & 1, bufW = bufR ^ 1;

        if (i < T) {
            for (int e = tid; e < 128 * INP; e += NTHREADS) {
                int row = e / INP, k = e - row * INP;
                sx[row * 12 + k] = __ldg(&x[((size_t)(gb0 + row) * T + i) * INP + k]);
            }
        }
        __syncthreads();   // sx visible; red buffer from prev iter free

        // This team's K half of all 9 chains: s0=hh0(a0), s1=hh1(a1), s2=ih1(a0)
        float acc[9][4] = {};
        {
            const uint4* pA0 = g_hA0 + ha_idx(bufR, gb, w2, ksB, 0, 0);
            const uint4* pA1 = g_hA1 + ha_idx(bufR, gb, w2, ksB, 0, 0);
#pragma unroll 2
            for (int ks = 0; ks < 8; ++ks) {
                uint4 a0h = __ldcg(pA0 + ks * 64 + l);
                uint4 a0l = __ldcg(pA0 + ks * 64 + 32 + l);
                uint4 a1h = __ldcg(pA1 + ks * 64 + l);
                uint4 a1l = __ldcg(pA1 + ks * 64 + 32 + l);
#pragma unroll
                for (int n = 0; n < 3; ++n) {
                    uint4 wb0 = sWB[((0 * 3 + n) * 16 + ksB + ks) * 32 + l];
                    mma_bf16(acc[0 + n], a0h.x, a0h.y, a0h.z, a0h.w, wb0.x, wb0.y);
                    mma_bf16(acc[0 + n], a0h.x, a0h.y, a0h.z, a0h.w, wb0.z, wb0.w);
                    mma_bf16(acc[0 + n], a0l.x, a0l.y, a0l.z, a0l.w, wb0.x, wb0.y);
                    uint4 wb1 = sWB[((1 * 3 + n) * 16 + ksB + ks) * 32 + l];
                    mma_bf16(acc[3 + n], a1h.x, a1h.y, a1h.z, a1h.w, wb1.x, wb1.y);
                    mma_bf16(acc[3 + n], a1h.x, a1h.y, a1h.z, a1h.w, wb1.z, wb1.w);
                    mma_bf16(acc[3 + n], a1l.x, a1l.y, a1l.z, a1l.w, wb1.x, wb1.y);
                    uint4 wb2 = sWB[((2 * 3 + n) * 16 + ksB + ks) * 32 + l];
                    mma_bf16(acc[6 + n], a0h.x, a0h.y, a0h.z, a0h.w, wb2.x, wb2.y);
                    mma_bf16(acc[6 + n], a0h.x, a0h.y, a0h.z, a0h.w, wb2.z, wb2.w);
                    mma_bf16(acc[6 + n], a0l.x, a0l.y, a0l.z, a0l.w, wb2.x, wb2.y);
                }
            }
        }

        // Cross-team reduction: team 1 publishes, team 0 accumulates.
        if (team) {
            float4* rp = reinterpret_cast<float4*>(red + t2 * 36);
#pragma unroll
            for (int q = 0; q < 9; ++q)
                rp[q] = *reinterpret_cast<float4*>(acc[q]);
        }
        __syncthreads();
        if (!team) {
            const float4* rp = reinterpret_cast<const float4*>(red + t2 * 36);
#pragma unroll
            for (int q = 0; q < 9; ++q) {
                float4 v = rp[q];
                acc[q][0] += v.x; acc[q][1] += v.y;
                acc[q][2] += v.z; acc[q][3] += v.w;
            }

            // Layer-0 update -> h0[i]; publish frags.
            if (i < T) {
#pragma unroll
                for (int p = 0; p < 4; ++p) {
                    int rb = p >> 1, sl = p & 1;
                    int lrow = w2 * 16 + g + 8 * rb;
                    int jc = 2 * c + sl;
                    float xr = 0.f, xz = 0.f, xn = 0.f;
#pragma unroll
                    for (int k = 0; k < INP; ++k) {
                        float xv = sx[lrow * 12 + k];
                        xr += xv * sWi0[(0 * 8 + jc) * 12 + k];
                        xz += xv * sWi0[(1 * 8 + jc) * 12 + k];
                        xn += xv * sWi0[(2 * 8 + jc) * 12 + k];
                    }
                    float rr = fsig(xr + sBi0[jc]     + acc[0][p] + sBh0[jc]);
                    float zz = fsig(xz + sBi0[8 + jc] + acc[1][p] + sBh0[8 + jc]);
                    float nn = ftanh_(xn + sBi0[16 + jc]
                                      + rr * (acc[2][p] + sBh0[16 + jc]));
                    h0reg[p] = (1.0f - zz) * nn + zz * h0reg[p];
                }
                unsigned hi01, lo01, hi23, lo23;
                split2(h0reg[0], h0reg[1], hi01, lo01);
                split2(h0reg[2], h0reg[3], hi23, lo23);
                char* bh = (char*)(g_hA0 + ha_idx(bufW, gb, w2, ksW, 0, l)) + wboff;
                char* bl = (char*)(g_hA0 + ha_idx(bufW, gb, w2, ksW, 1, l)) + wboff;
                __stcg((unsigned long long*)bh, ((unsigned long long)hi23 << 32) | hi01);
                __stcg((unsigned long long*)bl, ((unsigned long long)lo23 << 32) | lo01);
            }

            // Layer-1 update -> h1[i-1]; publish frags.
            if (i >= 1) {
#pragma unroll
                for (int p = 0; p < 4; ++p) {
                    int jc = 2 * c + (p & 1);
                    float rr = fsig(acc[6][p] + sBi1[jc]     + acc[3][p] + sBh1[jc]);
                    float zz = fsig(acc[7][p] + sBi1[8 + jc] + acc[4][p] + sBh1[8 + jc]);
                    float nn = ftanh_(acc[8][p] + sBi1[16 + jc]
                                      + rr * (acc[5][p] + sBh1[16 + jc]));
                    h1reg[p] = (1.0f - zz) * nn + zz * h1reg[p];
                }
                unsigned hi01, lo01, hi23, lo23;
                split2(h1reg[0], h1reg[1], hi01, lo01);
                split2(h1reg[2], h1reg[3], hi23, lo23);
                char* bh = (char*)(g_hA1 + ha_idx(bufW, gb, w2, ksW, 0, l)) + wboff;
                char* bl = (char*)(g_hA1 + ha_idx(bufW, gb, w2, ksW, 1, l)) + wboff;
                __stcg((unsigned long long*)bh, ((unsigned long long)hi23 << 32) | hi01);
                __stcg((unsigned long long*)bl, ((unsigned long long)lo23 << 32) | lo01);
                if (i == T) {
#pragma unroll
                    for (int p = 0; p < 4; ++p) {
                        int row = gb0 + w2 * 16 + g + 8 * (p >> 1);
                        int col = c0 + 2 * c + (p & 1);
                        __stcg(&g_hfin[(size_t)row * H + col], h1reg[p]);
                    }
                }
            }
        }

        barrier_sync(&g_cnt[gb], &g_gen[gb], GC);
    }

    // Epilogue needs h1 across all groups.
    barrier_sync(&g_cnt_all, &g_gen_all, NCTA);

    // ---- logits + softmax, one warp per batch row ----
    int gw = blockIdx.x * (NTHREADS / 32) + (tid >> 5);
    int lane = tid & 31;
    if (gw < B) {
        const float* hrow = g_hfin + (size_t)gw * H;
        float hk[8];
#pragma unroll
        for (int j2 = 0; j2 < 8; ++j2) hk[j2] = __ldcg(&hrow[lane + 32 * j2]);

        float logits[OUT];
#pragma unroll
        for (int o = 0; o < OUT; ++o) {
            float p = 0.0f;
#pragma unroll
            for (int j2 = 0; j2 < 8; ++j2)
                p += hk[j2] * __ldg(&W_out[o * H + lane + 32 * j2]);
#pragma unroll
            for (int s = 16; s > 0; s >>= 1)
                p += __shfl_xor_sync(0xffffffffu, p, s);
            logits[o] = p + __ldg(&b_out[o]);
        }
        float mx = logits[0];
#pragma unroll
        for (int o = 1; o < OUT; ++o) mx = fmaxf(mx, logits[o]);
        float sum = 0.0f;
#pragma unroll
        for (int o = 0; o < OUT; ++o) { logits[o] = expf(logits[o] - mx); sum += logits[o]; }
        float inv = 1.0f / sum;
        if (lane == 0) {
#pragma unroll
            for (int o = 0; o < OUT; ++o)
                out[(size_t)gw * OUT + o] = logits[o] * inv;
        }
    }
}

extern "C" void kernel_launch(void* const* d_in, const int* in_sizes, int n_in,
                              void* d_out, int out_size) {
    const float* x      = (const float*)d_in[0];
    // d_in[1] = times (unused), d_in[2] = interpolation_method (unused)
    const float* W_ih0  = (const float*)d_in[3];
    const float* W_hh0  = (const float*)d_in[4];
    const float* b_ih0  = (const float*)d_in[5];
    const float* b_hh0  = (const float*)d_in[6];
    const float* W_ih1  = (const float*)d_in[7];
    const float* W_hh1  = (const float*)d_in[8];
    const float* b_ih1  = (const float*)d_in[9];
    const float* b_hh1  = (const float*)d_in[10];
    const float* W_out  = (const float*)d_in[11];
    const float* b_out  = (const float*)d_in[12];
    float* out = (float*)d_out;

    const size_t smem_bytes = (size_t)NWB * 16
        + (size_t)(REDF + 128 * 12 + 24 * 12 + 4 * 24) * sizeof(float);  // ~116.5 KB
    cudaFuncSetAttribute(gru_tc_kernel,
                         cudaFuncAttributeMaxDynamicSharedMemorySize, (int)smem_bytes);

    gru_tc_kernel<<<NCTA, NTHREADS, smem_bytes>>>(
        x, W_ih0, W_hh0, b_ih0, b_hh0,
        W_ih1, W_hh1, b_ih1, b_hh1,
        W_out, b_out, out);
}

// round 11
// speedup vs baseline: 1.0384x; 1.0384x over previous
#include <cuda_runtime.h>
#include <cuda_bf16.h>
#include <math.h>

// Problem constants
#define B    512
#define T    365
#define INP  10
#define H    256
#define OUT  20

// 8 batch groups (64 rows) x 32 column groups (8 cols) = 256 persistent CTAs,
// 128 thr = 4 warps; warp w = M-tile (16 rows). Two CTAs co-resident per SM,
// nearly always from different (independent) batch groups -> latency overlap.
#define GB        8
#define GC        32
#define NCTA      (GB * GC)
#define NTHREADS  128

// A-fragment arrays: [buf2][gb8][mtile4][kstep16][split2][lane32] x uint4
#define HA_ELEMS  (2 * 8 * 4 * 16 * 2 * 32)

__device__ uint4 g_hA0[HA_ELEMS];
__device__ uint4 g_hA1[HA_ELEMS];
__device__ float g_hfin[B * H];
__device__ unsigned g_cnt[GB * 32];   // one cache line per group
__device__ unsigned g_gen[GB * 32];
__device__ unsigned g_cnt_all;
__device__ unsigned g_gen_all;

__device__ __forceinline__ int ha_idx(int buf, int gb, int mt, int ks, int sp, int l) {
    return (((((buf * 8 + gb) * 4 + mt) * 16 + ks) * 2 + sp) * 32 + l);
}

__device__ __forceinline__ void barrier_sync(unsigned* cnt, unsigned* gen, unsigned target) {
    __threadfence();
    __syncthreads();
    if (threadIdx.x == 0) {
        unsigned g = *(volatile unsigned*)gen;
        if (atomicAdd(cnt, 1u) == target - 1u) {
            *cnt = 0u;
            __threadfence();
            atomicAdd(gen, 1u);
        } else {
            while (*(volatile unsigned*)gen == g) { }
        }
    }
    __syncthreads();
}

// mma.sync m16n8k16 row.col f32.bf16.bf16.f32, accumulate in place.
__device__ __forceinline__ void mma_bf16(float* d, unsigned a0, unsigned a1,
                                         unsigned a2, unsigned a3,
                                         unsigned b0, unsigned b1) {
    asm volatile(
        "mma.sync.aligned.m16n8k16.row.col.f32.bf16.bf16.f32 "
        "{%0,%1,%2,%3}, {%4,%5,%6,%7}, {%8,%9}, {%0,%1,%2,%3};"
        : "+f"(d[0]), "+f"(d[1]), "+f"(d[2]), "+f"(d[3])
        : "r"(a0), "r"(a1), "r"(a2), "r"(a3), "r"(b0), "r"(b1));
}

// Split two fp32 into packed bf16x2 (hi) + packed bf16x2 (lo residual).
__device__ __forceinline__ void split2(float a, float b, unsigned& hi, unsigned& lo) {
    __nv_bfloat16 ah = __float2bfloat16_rn(a), bh = __float2bfloat16_rn(b);
    __nv_bfloat16 al = __float2bfloat16_rn(a - __bfloat162float(ah));
    __nv_bfloat16 bl = __float2bfloat16_rn(b - __bfloat162float(bh));
    __nv_bfloat162 h2; h2.x = ah; h2.y = bh;
    __nv_bfloat162 l2; l2.x = al; l2.y = bl;
    hi = *reinterpret_cast<unsigned*>(&h2);
    lo = *reinterpret_cast<unsigned*>(&l2);
}

// Fast gate math (MUFU-based; ~1e-6 error, tolerance 1e-3).
__device__ __forceinline__ float fsig(float v) {
    return 1.0f / (1.0f + __expf(-v));
}
__device__ __forceinline__ float ftanh_(float v) {
    return 2.0f / (1.0f + __expf(-2.0f * v)) - 1.0f;
}

// Weight frags: sets s (0=hh0, 1=hh1, 2=ih1) x 3 ntiles x 16 ksteps x 32 lanes,
// uint4 = {b0_hi, b1_hi, b0_lo, b1_lo}. 4608 x 16B = 72 KB.
#define NWB (3 * 3 * 16 * 32)
#define MBR 64   // batch rows per CTA

__global__ void __launch_bounds__(NTHREADS, 2)
gru_tc_kernel(const float* __restrict__ x,
              const float* __restrict__ W_ih0, const float* __restrict__ W_hh0,
              const float* __restrict__ b_ih0, const float* __restrict__ b_hh0,
              const float* __restrict__ W_ih1, const float* __restrict__ W_hh1,
              const float* __restrict__ b_ih1, const float* __restrict__ b_hh1,
              const float* __restrict__ W_out, const float* __restrict__ b_out,
              float* __restrict__ out) {
    extern __shared__ char smraw[];
    uint4* sWB  = reinterpret_cast<uint4*>(smraw);     // NWB x 16B
    float* sx   = reinterpret_cast<float*>(sWB + NWB); // MBR*12
    float* sWi0 = sx + MBR * 12;                       // 24*12
    float* sBi0 = sWi0 + 24 * 12;                      // 24 each
    float* sBh0 = sBi0 + 24;
    float* sBi1 = sBh0 + 24;
    float* sBh1 = sBi1 + 24;

    const int tid = threadIdx.x;
    const int w   = tid >> 5;              // warp = M-tile 0..3
    const int l   = tid & 31;              // lane
    const int g   = l >> 2;                // frag row group 0..7
    const int c   = l & 3;                 // frag col pair 0..3
    const int gb  = blockIdx.x >> 5;       // batch group 0..7
    const int gc  = blockIdx.x & 31;       // column group 0..31
    const int c0  = gc * 8;
    const int gb0 = gb * MBR;
    const int ksW = gc >> 1;               // kstep our h-cols land in
    const int wboff = 8 * (gc & 1);        // byte offset within 16B frag slot

    // ---- Prologue: pack weights into B-fragment layout (hi/lo split) ----
    {
        const float* Wsets[3] = { W_hh0, W_hh1, W_ih1 };
        for (int e = tid; e < NWB; e += NTHREADS) {
            int lane = e & 31;
            int ks   = (e >> 5) & 15;
            int rest = e >> 9;
            int n    = rest % 3;
            int s    = rest / 3;
            int t4 = lane & 3, nn = lane >> 2;
            const float* Wp = Wsets[s] + (size_t)(n * H + c0 + nn) * H + ks * 16;
            float w00 = Wp[2 * t4],     w01 = Wp[2 * t4 + 1];
            float w10 = Wp[8 + 2 * t4], w11 = Wp[9 + 2 * t4];
            uint4 v;
            split2(w00, w01, v.x, v.z);
            split2(w10, w11, v.y, v.w);
            sWB[e] = v;
        }
    }
    for (int idx = tid; idx < 24 * INP; idx += NTHREADS) {
        int row = idx / INP, i = idx - row * INP;
        int gg = row >> 3, j = row & 7;
        sWi0[row * 12 + i] = W_ih0[(gg * H + c0 + j) * INP + i];
    }
    if (tid < 24) {
        int gg = tid >> 3, j = tid & 7;
        int grow = gg * H + c0 + j;
        sBi0[tid] = b_ih0[grow];
        sBh0[tid] = b_hh0[grow];
        sBi1[tid] = b_ih1[grow];
        sBh1[tid] = b_hh1[grow];
    }

    // Zero A-frag buffers; every launch (determinism).
    {
        uint4 z4 = make_uint4(0u, 0u, 0u, 0u);
        for (int i = blockIdx.x * NTHREADS + tid; i < HA_ELEMS; i += NCTA * NTHREADS) {
            g_hA0[i] = z4;
            g_hA1[i] = z4;
        }
    }
    barrier_sync(&g_cnt_all, &g_gen_all, NCTA);

    // Per-thread persistent hidden state (4 D-frag positions).
    float h0reg[4] = {0.f, 0.f, 0.f, 0.f};
    float h1reg[4] = {0.f, 0.f, 0.f, 0.f};

    unsigned* gcnt = &g_cnt[gb * 32];
    unsigned* ggen = &g_gen[gb * 32];

    // ---- Pipelined loop: iter i computes h0[i] AND h1[i-1]; one barrier/iter.
    for (int i = 0; i <= T; ++i) {
        const int bufR = i & 1, bufW = bufR ^ 1;

        if (i < T) {
            for (int e = tid; e < MBR * INP; e += NTHREADS) {
                int row = e / INP, k = e - row * INP;
                sx[row * 12 + k] = __ldg(&x[((size_t)(gb0 + row) * T + i) * INP + k]);
            }
            __syncthreads();
        }

        // One fused mma stream: acc[s*3+n]; s: 0=hh0(a0), 1=hh1(a1), 2=ih1(a0)
        float acc[9][4] = {};
        {
            const uint4* pA0 = g_hA0 + ha_idx(bufR, gb, w, 0, 0, 0);
            const uint4* pA1 = g_hA1 + ha_idx(bufR, gb, w, 0, 0, 0);
#pragma unroll 4
            for (int ks = 0; ks < 16; ++ks) {
                uint4 a0h = __ldcg(pA0 + ks * 64 + l);
                uint4 a0l = __ldcg(pA0 + ks * 64 + 32 + l);
                uint4 a1h = __ldcg(pA1 + ks * 64 + l);
                uint4 a1l = __ldcg(pA1 + ks * 64 + 32 + l);
#pragma unroll
                for (int n = 0; n < 3; ++n) {
                    uint4 wb0 = sWB[((0 * 3 + n) * 16 + ks) * 32 + l];
                    mma_bf16(acc[0 + n], a0h.x, a0h.y, a0h.z, a0h.w, wb0.x, wb0.y);
                    mma_bf16(acc[0 + n], a0h.x, a0h.y, a0h.z, a0h.w, wb0.z, wb0.w);
                    mma_bf16(acc[0 + n], a0l.x, a0l.y, a0l.z, a0l.w, wb0.x, wb0.y);
                    uint4 wb1 = sWB[((1 * 3 + n) * 16 + ks) * 32 + l];
                    mma_bf16(acc[3 + n], a1h.x, a1h.y, a1h.z, a1h.w, wb1.x, wb1.y);
                    mma_bf16(acc[3 + n], a1h.x, a1h.y, a1h.z, a1h.w, wb1.z, wb1.w);
                    mma_bf16(acc[3 + n], a1l.x, a1l.y, a1l.z, a1l.w, wb1.x, wb1.y);
                    uint4 wb2 = sWB[((2 * 3 + n) * 16 + ks) * 32 + l];
                    mma_bf16(acc[6 + n], a0h.x, a0h.y, a0h.z, a0h.w, wb2.x, wb2.y);
                    mma_bf16(acc[6 + n], a0h.x, a0h.y, a0h.z, a0h.w, wb2.z, wb2.w);
                    mma_bf16(acc[6 + n], a0l.x, a0l.y, a0l.z, a0l.w, wb2.x, wb2.y);
                }
            }
        }

        // Layer-0 update -> h0[i]; publish frags.
        if (i < T) {
#pragma unroll
            for (int p = 0; p < 4; ++p) {
                int rb = p >> 1, sl = p & 1;
                int lrow = w * 16 + g + 8 * rb;
                int jc = 2 * c + sl;
                float xr = 0.f, xz = 0.f, xn = 0.f;
#pragma unroll
                for (int k = 0; k < INP; ++k) {
                    float xv = sx[lrow * 12 + k];
                    xr += xv * sWi0[(0 * 8 + jc) * 12 + k];
                    xz += xv * sWi0[(1 * 8 + jc) * 12 + k];
                    xn += xv * sWi0[(2 * 8 + jc) * 12 + k];
                }
                float rr = fsig(xr + sBi0[jc]     + acc[0][p] + sBh0[jc]);
                float zz = fsig(xz + sBi0[8 + jc] + acc[1][p] + sBh0[8 + jc]);
                float nn = ftanh_(xn + sBi0[16 + jc] + rr * (acc[2][p] + sBh0[16 + jc]));
                h0reg[p] = (1.0f - zz) * nn + zz * h0reg[p];
            }
            unsigned hi01, lo01, hi23, lo23;
            split2(h0reg[0], h0reg[1], hi01, lo01);
            split2(h0reg[2], h0reg[3], hi23, lo23);
            char* bh = (char*)(g_hA0 + ha_idx(bufW, gb, w, ksW, 0, l)) + wboff;
            char* bl = (char*)(g_hA0 + ha_idx(bufW, gb, w, ksW, 1, l)) + wboff;
            __stcg((unsigned long long*)bh, ((unsigned long long)hi23 << 32) | hi01);
            __stcg((unsigned long long*)bl, ((unsigned long long)lo23 << 32) | lo01);
        }

        // Layer-1 update -> h1[i-1]; publish frags.
        if (i >= 1) {
#pragma unroll
            for (int p = 0; p < 4; ++p) {
                int jc = 2 * c + (p & 1);
                float rr = fsig(acc[6][p] + sBi1[jc]     + acc[3][p] + sBh1[jc]);
                float zz = fsig(acc[7][p] + sBi1[8 + jc] + acc[4][p] + sBh1[8 + jc]);
                float nn = ftanh_(acc[8][p] + sBi1[16 + jc]
                                  + rr * (acc[5][p] + sBh1[16 + jc]));
                h1reg[p] = (1.0f - zz) * nn + zz * h1reg[p];
            }
            unsigned hi01, lo01, hi23, lo23;
            split2(h1reg[0], h1reg[1], hi01, lo01);
            split2(h1reg[2], h1reg[3], hi23, lo23);
            char* bh = (char*)(g_hA1 + ha_idx(bufW, gb, w, ksW, 0, l)) + wboff;
            char* bl = (char*)(g_hA1 + ha_idx(bufW, gb, w, ksW, 1, l)) + wboff;
            __stcg((unsigned long long*)bh, ((unsigned long long)hi23 << 32) | hi01);
            __stcg((unsigned long long*)bl, ((unsigned long long)lo23 << 32) | lo01);
            if (i == T) {
#pragma unroll
                for (int p = 0; p < 4; ++p) {
                    int row = gb0 + w * 16 + g + 8 * (p >> 1);
                    int col = c0 + 2 * c + (p & 1);
                    __stcg(&g_hfin[(size_t)row * H + col], h1reg[p]);
                }
            }
        }

        barrier_sync(gcnt, ggen, GC);
    }

    // Epilogue needs h1 across all groups.
    barrier_sync(&g_cnt_all, &g_gen_all, NCTA);

    // ---- logits + softmax, one warp per batch row ----
    int gw = blockIdx.x * (NTHREADS / 32) + w;
    if (gw < B) {
        const float* hrow = g_hfin + (size_t)gw * H;
        float hk[8];
#pragma unroll
        for (int j2 = 0; j2 < 8; ++j2) hk[j2] = __ldcg(&hrow[l + 32 * j2]);

        float logits[OUT];
#pragma unroll
        for (int o = 0; o < OUT; ++o) {
            float p = 0.0f;
#pragma unroll
            for (int j2 = 0; j2 < 8; ++j2)
                p += hk[j2] * __ldg(&W_out[o * H + l + 32 * j2]);
#pragma unroll
            for (int s = 16; s > 0; s >>= 1)
                p += __shfl_xor_sync(0xffffffffu, p, s);
            logits[o] = p + __ldg(&b_out[o]);
        }
        float mx = logits[0];
#pragma unroll
        for (int o = 1; o < OUT; ++o) mx = fmaxf(mx, logits[o]);
        float sum = 0.0f;
#pragma unroll
        for (int o = 0; o < OUT; ++o) { logits[o] = expf(logits[o] - mx); sum += logits[o]; }
        float inv = 1.0f / sum;
        if (l == 0) {
#pragma unroll
            for (int o = 0; o < OUT; ++o)
                out[(size_t)gw * OUT + o] = logits[o] * inv;
        }
    }
}

extern "C" void kernel_launch(void* const* d_in, const int* in_sizes, int n_in,
                              void* d_out, int out_size) {
    const float* x      = (const float*)d_in[0];
    // d_in[1] = times (unused), d_in[2] = interpolation_method (unused)
    const float* W_ih0  = (const float*)d_in[3];
    const float* W_hh0  = (const float*)d_in[4];
    const float* b_ih0  = (const float*)d_in[5];
    const float* b_hh0  = (const float*)d_in[6];
    const float* W_ih1  = (const float*)d_in[7];
    const float* W_hh1  = (const float*)d_in[8];
    const float* b_ih1  = (const float*)d_in[9];
    const float* b_hh1  = (const float*)d_in[10];
    const float* W_out  = (const float*)d_in[11];
    const float* b_out  = (const float*)d_in[12];
    float* out = (float*)d_out;

    const size_t smem_bytes = (size_t)NWB * 16
        + (size_t)(MBR * 12 + 24 * 12 + 4 * 24) * sizeof(float);   // ~76.4 KB
    cudaFuncSetAttribute(gru_tc_kernel,
                         cudaFuncAttributeMaxDynamicSharedMemorySize, (int)smem_bytes);

    gru_tc_kernel<<<NCTA, NTHREADS, smem_bytes>>>(
        x, W_ih0, W_hh0, b_ih0, b_hh0,
        W_ih1, W_hh1, b_ih1, b_hh1,
        W_out, b_out, out);
}

// round 12
// speedup vs baseline: 1.0832x; 1.0432x over previous
#include <cuda_runtime.h>
#include <cuda_bf16.h>
#include <math.h>

// Problem constants
#define B    512
#define T    365
#define INP  10
#define H    256
#define OUT  20

// 4 batch groups (128 rows) x 32 column groups (8 cols) = 128 persistent CTAs,
// 256 thr = 8 warps; warp w = M-tile (16 rows). NO group barriers: warp-granular
// producer/consumer counters per (gb, mtile, kstep).
#define GB        4
#define GC        32
#define NCTA      (GB * GC)
#define NTHREADS  256

// A-fragment arrays: [buf2][gb4][mtile8][kstep16][split2][lane32] x uint4
#define HA_ELEMS  (2 * 4 * 8 * 16 * 2 * 32)

__device__ uint4 g_hA0[HA_ELEMS];
__device__ uint4 g_hA1[HA_ELEMS];
__device__ float g_hfin[B * H];
// Publish counters: [gb][mt][16 ks + 16 pad] -> one 128B line per (gb,mt).
__device__ __align__(128) unsigned g_cnt0[GB][8][32];
__device__ __align__(128) unsigned g_cnt1[GB][8][32];
__device__ unsigned g_cnt_all;
__device__ unsigned g_gen_all;

__device__ __forceinline__ int ha_idx(int buf, int gb, int mt, int ks, int sp, int l) {
    return (((((buf * 4 + gb) * 8 + mt) * 16 + ks) * 2 + sp) * 32 + l);
}

__device__ __forceinline__ void barrier_sync(unsigned* cnt, unsigned* gen, unsigned target) {
    __threadfence();
    __syncthreads();
    if (threadIdx.x == 0) {
        unsigned g = *(volatile unsigned*)gen;
        if (atomicAdd(cnt, 1u) == target - 1u) {
            *cnt = 0u;
            __threadfence();
            atomicAdd(gen, 1u);
        } else {
            while (*(volatile unsigned*)gen == g) { }
        }
    }
    __syncthreads();
}

// All-lane poll: lane l watches counter (l&15); pass when all 16 >= target.
__device__ __forceinline__ void poll16(const unsigned* cb, unsigned target, int l) {
    const unsigned* p = cb + (l & 15);
    unsigned v;
    do {
        asm volatile("ld.acquire.gpu.global.u32 %0, [%1];" : "=r"(v) : "l"(p) : "memory");
    } while (!__all_sync(0xffffffffu, v >= target));
}

// Producer publish: fence own stores, warp-converge, lane0 RED +1.
__device__ __forceinline__ void publish_cnt(unsigned* cnt, int l) {
    __threadfence();
    __syncwarp();
    if (l == 0) atomicAdd(cnt, 1u);   // no return use -> RED
}

// mma.sync m16n8k16 row.col f32.bf16.bf16.f32, accumulate in place.
__device__ __forceinline__ void mma_bf16(float* d, unsigned a0, unsigned a1,
                                         unsigned a2, unsigned a3,
                                         unsigned b0, unsigned b1) {
    asm volatile(
        "mma.sync.aligned.m16n8k16.row.col.f32.bf16.bf16.f32 "
        "{%0,%1,%2,%3}, {%4,%5,%6,%7}, {%8,%9}, {%0,%1,%2,%3};"
        : "+f"(d[0]), "+f"(d[1]), "+f"(d[2]), "+f"(d[3])
        : "r"(a0), "r"(a1), "r"(a2), "r"(a3), "r"(b0), "r"(b1));
}

// Split two fp32 into packed bf16x2 (hi) + packed bf16x2 (lo residual).
__device__ __forceinline__ void split2(float a, float b, unsigned& hi, unsigned& lo) {
    __nv_bfloat16 ah = __float2bfloat16_rn(a), bh = __float2bfloat16_rn(b);
    __nv_bfloat16 al = __float2bfloat16_rn(a - __bfloat162float(ah));
    __nv_bfloat16 bl = __float2bfloat16_rn(b - __bfloat162float(bh));
    __nv_bfloat162 h2; h2.x = ah; h2.y = bh;
    __nv_bfloat162 l2; l2.x = al; l2.y = bl;
    hi = *reinterpret_cast<unsigned*>(&h2);
    lo = *reinterpret_cast<unsigned*>(&l2);
}

// Fast gate math (MUFU-based; ~1e-6 error vs 1e-3 tolerance).
__device__ __forceinline__ float fsig(float v) {
    return 1.0f / (1.0f + __expf(-v));
}
__device__ __forceinline__ float ftanh_(float v) {
    return 2.0f / (1.0f + __expf(-2.0f * v)) - 1.0f;
}

// Weight frags: sets s (0=hh0, 1=hh1, 2=ih1) x 3 ntiles x 16 ksteps x 32 lanes,
// uint4 = {b0_hi, b1_hi, b0_lo, b1_lo}. 4608 x 16B = 72 KB.
#define NWB (3 * 3 * 16 * 32)

__global__ void __launch_bounds__(NTHREADS, 1)
gru_tc_kernel(const float* __restrict__ x,
              const float* __restrict__ W_ih0, const float* __restrict__ W_hh0,
              const float* __restrict__ b_ih0, const float* __restrict__ b_hh0,
              const float* __restrict__ W_ih1, const float* __restrict__ W_hh1,
              const float* __restrict__ b_ih1, const float* __restrict__ b_hh1,
              const float* __restrict__ W_out, const float* __restrict__ b_out,
              float* __restrict__ out) {
    extern __shared__ char smraw[];
    uint4* sWB  = reinterpret_cast<uint4*>(smraw);     // NWB x 16B
    float* sx   = reinterpret_cast<float*>(sWB + NWB); // 8 warps x 192
    float* sWi0 = sx + 8 * 192;                        // 24*12
    float* sBi0 = sWi0 + 24 * 12;                      // 24 each
    float* sBh0 = sBi0 + 24;
    float* sBi1 = sBh0 + 24;
    float* sBh1 = sBi1 + 24;

    const int tid = threadIdx.x;
    const int w   = tid >> 5;              // warp = M-tile 0..7
    const int l   = tid & 31;              // lane
    const int g   = l >> 2;                // frag row group 0..7
    const int c   = l & 3;                 // frag col pair 0..3
    const int gb  = blockIdx.x >> 5;       // batch group
    const int gc  = blockIdx.x & 31;       // column group
    const int c0  = gc * 8;
    const int gb0 = gb * 128;
    const int ksW = gc >> 1;               // kstep our h-cols land in
    const int wboff = 8 * (gc & 1);        // byte offset within 16B frag slot

    unsigned* myCnt0 = &g_cnt0[gb][w][ksW];
    unsigned* myCnt1 = &g_cnt1[gb][w][ksW];
    const unsigned* pollC0 = &g_cnt0[gb][w][0];
    const unsigned* pollC1 = &g_cnt1[gb][w][0];

    // ---- Prologue: pack weights into B-fragment layout (hi/lo split) ----
    {
        const float* Wsets[3] = { W_hh0, W_hh1, W_ih1 };
        for (int e = tid; e < NWB; e += NTHREADS) {
            int lane = e & 31;
            int ks   = (e >> 5) & 15;
            int rest = e >> 9;
            int n    = rest % 3;
            int s    = rest / 3;
            int t4 = lane & 3, nn = lane >> 2;
            const float* Wp = Wsets[s] + (size_t)(n * H + c0 + nn) * H + ks * 16;
            float w00 = Wp[2 * t4],     w01 = Wp[2 * t4 + 1];
            float w10 = Wp[8 + 2 * t4], w11 = Wp[9 + 2 * t4];
            uint4 v;
            split2(w00, w01, v.x, v.z);
            split2(w10, w11, v.y, v.w);
            sWB[e] = v;
        }
    }
    for (int idx = tid; idx < 24 * INP; idx += NTHREADS) {
        int row = idx / INP, i = idx - row * INP;
        int gg = row >> 3, j = row & 7;
        sWi0[row * 12 + i] = W_ih0[(gg * H + c0 + j) * INP + i];
    }
    if (tid < 24) {
        int gg = tid >> 3, j = tid & 7;
        int grow = gg * H + c0 + j;
        sBi0[tid] = b_ih0[grow];
        sBh0[tid] = b_hh0[grow];
        sBi1[tid] = b_ih1[grow];
        sBh1[tid] = b_hh1[grow];
    }

    // Zero A-frag buffers + counters; every launch (determinism).
    {
        uint4 z4 = make_uint4(0u, 0u, 0u, 0u);
        for (int i = blockIdx.x * NTHREADS + tid; i < HA_ELEMS; i += NCTA * NTHREADS) {
            g_hA0[i] = z4;
            g_hA1[i] = z4;
        }
        unsigned* c0p = &g_cnt0[0][0][0];
        unsigned* c1p = &g_cnt1[0][0][0];
        for (int i = blockIdx.x * NTHREADS + tid; i < GB * 8 * 32; i += NCTA * NTHREADS) {
            c0p[i] = 0u;
            c1p[i] = 0u;
        }
    }
    barrier_sync(&g_cnt_all, &g_gen_all, NCTA);

    // Per-thread persistent hidden state (4 D-frag positions).
    float h0reg[4] = {0.f, 0.f, 0.f, 0.f};
    float h1reg[4] = {0.f, 0.f, 0.f, 0.f};

    // ---- Warp-autonomous pipelined loop (no CTA/grid barriers inside) ----
    for (int i = 0; i <= T; ++i) {
        const int bufR = i & 1, bufW = bufR ^ 1;

        // Stage x[i] for this warp's 16 rows (independent of counters).
        if (i < T) {
            float* sxw = sx + w * 192;
            for (int e = l; e < 16 * INP; e += 32) {
                int row = e / INP, k = e - row * INP;
                sxw[row * 12 + k] =
                    __ldg(&x[((size_t)(gb0 + w * 16 + row) * T + i) * INP + k]);
            }
            __syncwarp();
        }

        // ===== Phase A: needs h0[i-1] (published by producers' phase A of i-1).
        poll16(pollC0, 2u * (unsigned)i, l);

        float accA[6][4] = {};   // [0..2]=hh0, [3..5]=ih1
        {
            const uint4* pA0 = g_hA0 + ha_idx(bufR, gb, w, 0, 0, 0);
#pragma unroll 4
            for (int ks = 0; ks < 16; ++ks) {
                uint4 a0h = __ldcg(pA0 + ks * 64 + l);
                uint4 a0l = __ldcg(pA0 + ks * 64 + 32 + l);
#pragma unroll
                for (int n = 0; n < 3; ++n) {
                    uint4 wb0 = sWB[((0 * 3 + n) * 16 + ks) * 32 + l];
                    mma_bf16(accA[0 + n], a0h.x, a0h.y, a0h.z, a0h.w, wb0.x, wb0.y);
                    mma_bf16(accA[0 + n], a0h.x, a0h.y, a0h.z, a0h.w, wb0.z, wb0.w);
                    mma_bf16(accA[0 + n], a0l.x, a0l.y, a0l.z, a0l.w, wb0.x, wb0.y);
                    uint4 wb2 = sWB[((2 * 3 + n) * 16 + ks) * 32 + l];
                    mma_bf16(accA[3 + n], a0h.x, a0h.y, a0h.z, a0h.w, wb2.x, wb2.y);
                    mma_bf16(accA[3 + n], a0h.x, a0h.y, a0h.z, a0h.w, wb2.z, wb2.w);
                    mma_bf16(accA[3 + n], a0l.x, a0l.y, a0l.z, a0l.w, wb2.x, wb2.y);
                }
            }
        }

        // Layer-0 update -> h0[i]; publish frags + counter EARLY.
        if (i < T) {
            const float* sxw = sx + w * 192;
#pragma unroll
            for (int p = 0; p < 4; ++p) {
                int rb = p >> 1, sl = p & 1;
                int lrow = g + 8 * rb;              // row within warp tile
                int jc = 2 * c + sl;
                float xr = 0.f, xz = 0.f, xn = 0.f;
#pragma unroll
                for (int k = 0; k < INP; ++k) {
                    float xv = sxw[lrow * 12 + k];
                    xr += xv * sWi0[(0 * 8 + jc) * 12 + k];
                    xz += xv * sWi0[(1 * 8 + jc) * 12 + k];
                    xn += xv * sWi0[(2 * 8 + jc) * 12 + k];
                }
                float rr = fsig(xr + sBi0[jc]     + accA[0][p] + sBh0[jc]);
                float zz = fsig(xz + sBi0[8 + jc] + accA[1][p] + sBh0[8 + jc]);
                float nn = ftanh_(xn + sBi0[16 + jc]
                                  + rr * (accA[2][p] + sBh0[16 + jc]));
                h0reg[p] = (1.0f - zz) * nn + zz * h0reg[p];
            }
            unsigned hi01, lo01, hi23, lo23;
            split2(h0reg[0], h0reg[1], hi01, lo01);
            split2(h0reg[2], h0reg[3], hi23, lo23);
            char* bh = (char*)(g_hA0 + ha_idx(bufW, gb, w, ksW, 0, l)) + wboff;
            char* bl = (char*)(g_hA0 + ha_idx(bufW, gb, w, ksW, 1, l)) + wboff;
            __stcg((unsigned long long*)bh, ((unsigned long long)hi23 << 32) | hi01);
            __stcg((unsigned long long*)bl, ((unsigned long long)lo23 << 32) | lo01);
            publish_cnt(myCnt0, l);
        }

        // ===== Phase B: needs h1[i-2] (published by producers' phase B of i-1).
        if (i >= 1) {
            poll16(pollC1, 2u * (unsigned)(i - 1), l);

            float accC[3][4] = {};
            {
                const uint4* pA1 = g_hA1 + ha_idx(bufR, gb, w, 0, 0, 0);
#pragma unroll 4
                for (int ks = 0; ks < 16; ++ks) {
                    uint4 a1h = __ldcg(pA1 + ks * 64 + l);
                    uint4 a1l = __ldcg(pA1 + ks * 64 + 32 + l);
#pragma unroll
                    for (int n = 0; n < 3; ++n) {
                        uint4 wb1 = sWB[((1 * 3 + n) * 16 + ks) * 32 + l];
                        mma_bf16(accC[n], a1h.x, a1h.y, a1h.z, a1h.w, wb1.x, wb1.y);
                        mma_bf16(accC[n], a1h.x, a1h.y, a1h.z, a1h.w, wb1.z, wb1.w);
                        mma_bf16(accC[n], a1l.x, a1l.y, a1l.z, a1l.w, wb1.x, wb1.y);
                    }
                }
            }

            // Layer-1 update -> h1[i-1]; publish frags + counter.
#pragma unroll
            for (int p = 0; p < 4; ++p) {
                int jc = 2 * c + (p & 1);
                float rr = fsig(accA[3][p] + sBi1[jc]     + accC[0][p] + sBh1[jc]);
                float zz = fsig(accA[4][p] + sBi1[8 + jc] + accC[1][p] + sBh1[8 + jc]);
                float nn = ftanh_(accA[5][p] + sBi1[16 + jc]
                                  + rr * (accC[2][p] + sBh1[16 + jc]));
                h1reg[p] = (1.0f - zz) * nn + zz * h1reg[p];
            }
            unsigned hi01, lo01, hi23, lo23;
            split2(h1reg[0], h1reg[1], hi01, lo01);
            split2(h1reg[2], h1reg[3], hi23, lo23);
            char* bh = (char*)(g_hA1 + ha_idx(bufW, gb, w, ksW, 0, l)) + wboff;
            char* bl = (char*)(g_hA1 + ha_idx(bufW, gb, w, ksW, 1, l)) + wboff;
            __stcg((unsigned long long*)bh, ((unsigned long long)hi23 << 32) | hi01);
            __stcg((unsigned long long*)bl, ((unsigned long long)lo23 << 32) | lo01);
            publish_cnt(myCnt1, l);

            if (i == T) {
#pragma unroll
                for (int p = 0; p < 4; ++p) {
                    int row = gb0 + w * 16 + g + 8 * (p >> 1);
                    int col = c0 + 2 * c + (p & 1);
                    __stcg(&g_hfin[(size_t)row * H + col], h1reg[p]);
                }
            }
        }
    }

    // Epilogue needs h1 across all groups.
    barrier_sync(&g_cnt_all, &g_gen_all, NCTA);

    // ---- logits + softmax, one warp per batch row ----
    int gw = blockIdx.x * (NTHREADS / 32) + w;
    if (gw < B) {
        const float* hrow = g_hfin + (size_t)gw * H;
        float hk[8];
#pragma unroll
        for (int j2 = 0; j2 < 8; ++j2) hk[j2] = __ldcg(&hrow[l + 32 * j2]);

        float logits[OUT];
#pragma unroll
        for (int o = 0; o < OUT; ++o) {
            float p = 0.0f;
#pragma unroll
            for (int j2 = 0; j2 < 8; ++j2)
                p += hk[j2] * __ldg(&W_out[o * H + l + 32 * j2]);
#pragma unroll
            for (int s = 16; s > 0; s >>= 1)
                p += __shfl_xor_sync(0xffffffffu, p, s);
            logits[o] = p + __ldg(&b_out[o]);
        }
        float mx = logits[0];
#pragma unroll
        for (int o = 1; o < OUT; ++o) mx = fmaxf(mx, logits[o]);
        float sum = 0.0f;
#pragma unroll
        for (int o = 0; o < OUT; ++o) { logits[o] = expf(logits[o] - mx); sum += logits[o]; }
        float inv = 1.0f / sum;
        if (l == 0) {
#pragma unroll
            for (int o = 0; o < OUT; ++o)
                out[(size_t)gw * OUT + o] = logits[o] * inv;
        }
    }
}

extern "C" void kernel_launch(void* const* d_in, const int* in_sizes, int n_in,
                              void* d_out, int out_size) {
    const float* x      = (const float*)d_in[0];
    // d_in[1] = times (unused), d_in[2] = interpolation_method (unused)
    const float* W_ih0  = (const float*)d_in[3];
    const float* W_hh0  = (const float*)d_in[4];
    const float* b_ih0  = (const float*)d_in[5];
    const float* b_hh0  = (const float*)d_in[6];
    const float* W_ih1  = (const float*)d_in[7];
    const float* W_hh1  = (const float*)d_in[8];
    const float* b_ih1  = (const float*)d_in[9];
    const float* b_hh1  = (const float*)d_in[10];
    const float* W_out  = (const float*)d_in[11];
    const float* b_out  = (const float*)d_in[12];
    float* out = (float*)d_out;

    const size_t smem_bytes = (size_t)NWB * 16
        + (size_t)(8 * 192 + 24 * 12 + 4 * 24) * sizeof(float);   // ~80 KB
    cudaFuncSetAttribute(gru_tc_kernel,
                         cudaFuncAttributeMaxDynamicSharedMemorySize, (int)smem_bytes);

    gru_tc_kernel<<<NCTA, NTHREADS, smem_bytes>>>(
        x, W_ih0, W_hh0, b_ih0, b_hh0,
        W_ih1, W_hh1, b_ih1, b_hh1,
        W_out, b_out, out);
}